// round 11
// baseline (speedup 1.0000x reference)
#include <cuda_runtime.h>
#include <cstdint>

#define N_NODES 100000
#define E_MAX   1200000
#define HID 64

// ---- static device scratch (allocation-free) ----
__device__ float g_deg [N_NODES];            // sum of incoming edge weights (no self)
__device__ float g_hs  [N_NODES * HID];      // raw transformed features (XW)
__device__ float g_act [N_NODES * HID];      // layer-1 activations
__device__ int   g_cnt [N_NODES];            // in-degree count
__device__ int   g_offs[N_NODES];            // CSR exclusive offsets
__device__ int   g_cur [N_NODES];            // binning cursors
__device__ int   g_bsum[512];                // per-block count sums
__device__ int   g_done1;                    // scan phase-1 flag (zeroed in init)
__device__ int   g_done2;                    // scan phase-2 flag (zeroed in init)
__device__ int2  g_csr [E_MAX];              // CSR entry: {src*HID, bits(w*dinv[src])}
__device__ int   g_is32;                     // edge_index dtype flag

// ---- packed f32x2 helpers (Blackwell FFMA2; PTX-only, ptxas won't fuse) ----
__device__ __forceinline__ unsigned long long pack2(float a, float b) {
    unsigned long long r;
    asm("mov.b64 %0, {%1, %2};" : "=l"(r)
        : "r"(__float_as_uint(a)), "r"(__float_as_uint(b)));
    return r;
}
__device__ __forceinline__ float2 unpack2(unsigned long long v) {
    unsigned lo, hi;
    asm("mov.b64 {%0, %1}, %2;" : "=r"(lo), "=r"(hi) : "l"(v));
    return make_float2(__uint_as_float(lo), __uint_as_float(hi));
}
__device__ __forceinline__ void fma2(unsigned long long& d,
                                     unsigned long long a, unsigned long long b) {
    asm("fma.rn.f32x2 %0, %1, %2, %3;" : "=l"(d) : "l"(a), "l"(b), "l"(d));
}

__device__ __forceinline__ void decode_edge(const void* ei, int E, int e,
                                            int& src, int& dst) {
    if (g_is32) {
        const int* p = (const int*)ei;
        src = p[e]; dst = p[E + e];
    } else {
        const long long* p = (const long long*)ei;
        src = (int)p[e]; dst = (int)p[E + e];
    }
}

// ---------------------------------------------------------------------------
// init: zero deg/cnt/flags, detect edge_index dtype.
// ---------------------------------------------------------------------------
__global__ void init_kernel(const void* ei, int n) {
    int i = blockIdx.x * blockDim.x + threadIdx.x;
    if (i < n) { g_deg[i] = 0.0f; g_cnt[i] = 0; }
    if (i == 0) {
        g_done1 = 0;
        g_done2 = 0;
        const long long* p = (const long long*)ei;
        int bad = 0;
        for (int k = 0; k < 64; k++) {
            long long v = p[k];
            if (v < 0 || v >= N_NODES) bad = 1;
        }
        g_is32 = bad;
    }
}

// ---------------------------------------------------------------------------
// Shared GEMM row body with packed FFMA2. Writes raw (unscaled) row to g_hs.
// ---------------------------------------------------------------------------
__device__ __forceinline__ void gemm_row_f32x2(
    const float* __restrict__ in_row, const float* sW, int row)
{
    unsigned long long acc2[HID / 2];
    #pragma unroll
    for (int j = 0; j < HID / 2; j++) acc2[j] = 0ULL;   // bits(+0.0f, +0.0f)

    const float4* xr = (const float4*)in_row;
    #pragma unroll
    for (int k4 = 0; k4 < HID / 4; k4++) {
        float4 xv = __ldg(&xr[k4]);
        float xs[4] = {xv.x, xv.y, xv.z, xv.w};
        #pragma unroll
        for (int s = 0; s < 4; s++) {
            int k = k4 * 4 + s;
            unsigned long long xk2 = pack2(xs[s], xs[s]);
            const ulonglong2* wp = (const ulonglong2*)&sW[k * HID];
            #pragma unroll
            for (int j2 = 0; j2 < HID / 4; j2++) {
                ulonglong2 wv = wp[j2];
                fma2(acc2[2 * j2 + 0], xk2, wv.x);
                fma2(acc2[2 * j2 + 1], xk2, wv.y);
            }
        }
    }

    float4* ph = (float4*)&g_hs[(size_t)row * HID];
    #pragma unroll
    for (int j4 = 0; j4 < HID / 4; j4++) {
        float2 p0 = unpack2(acc2[2 * j4 + 0]);
        float2 p1 = unpack2(acc2[2 * j4 + 1]);
        ph[j4] = make_float4(p0.x, p0.y, p1.x, p1.y);
    }
}

// ---------------------------------------------------------------------------
// Fused: blocks [0, gE) run the edge histogram (cnt++/deg+=w atomics);
// blocks [gE, gE+gN) run the layer-1 GEMM rows (hs = x @ W1, unscaled).
// ---------------------------------------------------------------------------
__global__ __launch_bounds__(256) void hist_gemm1_kernel(
    const void* ei, const float* __restrict__ w,
    const float* __restrict__ x, const float* __restrict__ W,
    int n, int E, int gE)
{
    if ((int)blockIdx.x < gE) {
        int e = blockIdx.x * blockDim.x + threadIdx.x;
        if (e >= E) return;
        int src, dst;
        decode_edge(ei, E, e, src, dst);
        atomicAdd(&g_cnt[dst], 1);
        atomicAdd(&g_deg[dst], w[e]);
        return;
    }

    __shared__ __align__(16) float sW[HID * HID];
    for (int i = threadIdx.x; i < HID * HID; i += blockDim.x) sW[i] = W[i];
    __syncthreads();

    int row = (blockIdx.x - gE) * blockDim.x + threadIdx.x;
    if (row >= n) return;
    gemm_row_f32x2(x + (size_t)row * HID, sW, row);
}

// ---------------------------------------------------------------------------
// Fused scan + bin, one kernel (grid = gE blocks). Deadlock-free: the
// nsb=391 scan blocks all fit in wave 1.
// ---------------------------------------------------------------------------
__global__ __launch_bounds__(256) void scanbin_kernel(
    const void* ei, const float* __restrict__ w, int n, int E, int nsb)
{
    __shared__ int s[256];
    int t = threadIdx.x;
    int bid = blockIdx.x;

    if (bid < nsb) {
        int i = bid * 256 + t;
        int v = (i < n) ? g_cnt[i] : 0;
        s[t] = v; __syncthreads();
        #pragma unroll
        for (int d = 1; d < 256; d <<= 1) {
            int x = (t >= d) ? s[t - d] : 0;
            __syncthreads();
            s[t] += x; __syncthreads();
        }
        int excl = s[t] - v;                    // exclusive within block

        if (t == 255) {
            g_bsum[bid] = s[255];
            __threadfence();
            atomicAdd(&g_done1, 1);
        }
        if (t == 0) {
            while (atomicAdd(&g_done1, 0) < nsb) __nanosleep(64);
        }
        __syncthreads();

        int p = 0;
        for (int b = t; b < bid; b += 256) p += g_bsum[b];
        s[t] = p; __syncthreads();
        #pragma unroll
        for (int d = 128; d > 0; d >>= 1) {
            if (t < d) s[t] += s[t + d];
            __syncthreads();
        }
        int prefix = s[0];
        if (i < n) {
            int o = excl + prefix;
            g_offs[i] = o;
            g_cur[i]  = o;
        }
        __syncthreads();
        if (t == 0) {
            __threadfence();
            atomicAdd(&g_done2, 1);
        }
    }

    // ---- phase B: everyone waits for all cursors, then bins ----
    if (t == 0) {
        while (atomicAdd(&g_done2, 0) < nsb) __nanosleep(64);
    }
    __syncthreads();

    int e = bid * 256 + t;
    if (e >= E) return;
    int src, dst;
    decode_edge(ei, E, e, src, dst);
    float wn = w[e] * rsqrtf(1.0f + g_deg[src]);
    int pos = atomicAdd(&g_cur[dst], 1);
    g_csr[pos] = make_int2(src * HID, __float_as_int(wn));  // pre-multiplied idx
}

// ---------------------------------------------------------------------------
// Layer-2 GEMM: hs = g_act @ W2 (raw). g_act referenced inside device code.
// ---------------------------------------------------------------------------
__global__ __launch_bounds__(256) void gemm2_kernel(
    const float* __restrict__ W, int n)
{
    __shared__ __align__(16) float sW[HID * HID];
    for (int i = threadIdx.x; i < HID * HID; i += blockDim.x) sW[i] = W[i];
    __syncthreads();

    int row = blockIdx.x * blockDim.x + threadIdx.x;
    if (row >= n) return;
    gemm_row_f32x2((const float*)g_act + (size_t)row * HID, sW, row);
}

// ---------------------------------------------------------------------------
// Aggregation: one warp per dst. Lane l owns features [2l, 2l+1] packed.
// Shuffle-free: all lanes issue the SAME CSR address (warp-uniform LDG ->
// one L1 wavefront broadcast, sequential -> 15/16 L1 hit). 4 independent
// accumulator chains keep 8 loads in flight.
//   MODE 0: g_act = relu(dinv*acc + bias);  MODE 1: outp = dinv*acc + bias
// ---------------------------------------------------------------------------
template <int MODE>
__global__ __launch_bounds__(256) void agg_kernel(
    const float* __restrict__ bias, float* __restrict__ outp, int n)
{
    int gtid = blockIdx.x * blockDim.x + threadIdx.x;
    int dst  = gtid >> 5;
    if (dst >= n) return;
    int lane = threadIdx.x & 31;

    int beg = g_offs[dst];
    int cnt = g_cnt[dst];
    float di = rsqrtf(1.0f + g_deg[dst]);

    const float* hsl = g_hs + lane * 2;        // lane-offset base

    float2 hself = *(const float2*)(hsl + (size_t)dst * HID);
    unsigned long long accA = pack2(di * hself.x, di * hself.y);  // self-loop
    unsigned long long accB = 0ULL, accC = 0ULL, accD = 0ULL;

    int t = 0;
    for (; t + 4 <= cnt; t += 4) {
        int2 e0 = __ldg(&g_csr[beg + t + 0]);
        int2 e1 = __ldg(&g_csr[beg + t + 1]);
        int2 e2 = __ldg(&g_csr[beg + t + 2]);
        int2 e3 = __ldg(&g_csr[beg + t + 3]);
        unsigned long long h0 = __ldg((const unsigned long long*)(hsl + e0.x));
        unsigned long long h1 = __ldg((const unsigned long long*)(hsl + e1.x));
        unsigned long long h2 = __ldg((const unsigned long long*)(hsl + e2.x));
        unsigned long long h3 = __ldg((const unsigned long long*)(hsl + e3.x));
        float w0 = __int_as_float(e0.y), w1 = __int_as_float(e1.y);
        float w2 = __int_as_float(e2.y), w3 = __int_as_float(e3.y);
        fma2(accA, pack2(w0, w0), h0);
        fma2(accB, pack2(w1, w1), h1);
        fma2(accC, pack2(w2, w2), h2);
        fma2(accD, pack2(w3, w3), h3);
    }
    for (; t < cnt; t++) {
        int2 e0 = __ldg(&g_csr[beg + t]);
        unsigned long long h0 = __ldg((const unsigned long long*)(hsl + e0.x));
        float w0 = __int_as_float(e0.y);
        fma2(accA, pack2(w0, w0), h0);
    }

    float2 a = unpack2(accA);
    float2 b = unpack2(accB);
    float2 c = unpack2(accC);
    float2 d = unpack2(accD);
    float ax = (a.x + b.x) + (c.x + d.x);
    float ay = (a.y + b.y) + (c.y + d.y);
    float bx = bias[lane * 2], by = bias[lane * 2 + 1];
    float ox = di * ax + bx;
    float oy = di * ay + by;
    if (MODE == 0) {
        ox = fmaxf(ox, 0.0f);
        oy = fmaxf(oy, 0.0f);
        *(float2*)&g_act[(size_t)dst * HID + lane * 2] = make_float2(ox, oy);
    } else {
        *(float2*)&outp[(size_t)dst * HID + lane * 2] = make_float2(ox, oy);
    }
}

extern "C" void kernel_launch(void* const* d_in, const int* in_sizes, int n_in,
                              void* d_out, int out_size)
{
    const float* x  = (const float*)d_in[0];
    const void*  ei = d_in[1];               // int32 or int64, device-detected
    const float* ew = (const float*)d_in[2];
    const float* W1 = (const float*)d_in[3];
    const float* b1 = (const float*)d_in[4];
    const float* W2 = (const float*)d_in[5];
    const float* b2 = (const float*)d_in[6];
    float* out = (float*)d_out;

    int n = in_sizes[0] / HID;
    int E = in_sizes[2];

    const int T = 256;
    int gN   = (n + T - 1) / T;              // 391
    int gE   = (E + T - 1) / T;              // 4688
    int gN32 = (n * 32 + T - 1) / T;         // warp-per-node

    init_kernel      <<<gN, T>>>(ei, n);                         // 0
    hist_gemm1_kernel<<<gE + gN, T>>>(ei, ew, x, W1, n, E, gE);  // 1
    scanbin_kernel   <<<gE, T>>>(ei, ew, n, E, gN);              // 2

    agg_kernel<0><<<gN32, T>>>(b1, nullptr, n);                  // 3 (profiled)
    gemm2_kernel <<<gN, T>>>(W2, n);                             // 4
    agg_kernel<1><<<gN32, T>>>(b2, out, n);                      // 5
}